// round 9
// baseline (speedup 1.0000x reference)
#include <cuda_runtime.h>
#include <cuda_fp16.h>
#include <cstdint>

#define N_ROWS  131072
#define C_DIM   256
#define K_CODES 1024
#define NZQ     33554432
#define HWSZ    4096
#define ROWS_CTA 64
#define GRID    (N_ROWS / ROWS_CTA)

#define ESCALE    4096.0f          // 2^12: lift emb splits out of fp16 subnormal range
#define EINVSCALE 0.000244140625f  // 2^-12 (exact)

__device__ __half g_es[2u * K_CODES * C_DIM];   // emb fp16 2-splits of (e * 2^12)
__device__ float  g_e2[K_CODES];
__device__ float  g_partial[GRID];

__device__ __forceinline__ uint32_t smem_u32(const void* p){
  uint32_t a;
  asm("{ .reg .u64 t; cvta.to.shared.u64 t, %1; cvt.u32.u64 %0, t; }" : "=r"(a) : "l"(p));
  return a;
}
__device__ __forceinline__ uint32_t swz(uint32_t off){ return off ^ ((off >> 3) & 0x70); }

__device__ __forceinline__ void split2(float v, uint32_t &s0, uint32_t &s1){
  __half h0 = __float2half_rn(v);
  float r  = __fsub_rn(v, __half2float(h0));
  __half h1 = __float2half_rn(r);
  s0 = (uint32_t)__half_as_ushort(h0);
  s1 = (uint32_t)__half_as_ushort(h1);
}

#define CPASYNC16(dst, src) \
  asm volatile("cp.async.cg.shared.global [%0], [%1], 16;" :: "r"(dst), "l"(src))
#define CPCOMMIT() asm volatile("cp.async.commit_group;")

#define LDSM_X4(r0,r1,r2,r3,addr) \
  asm volatile("ldmatrix.sync.aligned.m8n8.x4.shared.b16 {%0,%1,%2,%3}, [%4];" \
    : "=r"(r0), "=r"(r1), "=r"(r2), "=r"(r3) : "r"(addr))

#define MMA16816(c0,c1,c2,c3,a0,a1,a2,a3,b0,b1) \
  asm volatile("mma.sync.aligned.m16n8k16.row.col.f32.f16.f16.f32 " \
    "{%0,%1,%2,%3}, {%4,%5,%6,%7}, {%8,%9}, {%0,%1,%2,%3};" \
    : "+f"(c0), "+f"(c1), "+f"(c2), "+f"(c3) \
    : "r"(a0), "r"(a1), "r"(a2), "r"(a3), "r"(b0), "r"(b1))

#define STS128(addr, a0, a1, a2, a3) \
  asm volatile("st.shared.v4.b32 [%0], {%1,%2,%3,%4};" :: "r"(addr), "r"(a0), "r"(a1), "r"(a2), "r"(a3) : "memory")

// ---------------- prep: emb fp16 splits (scaled) + ||e||^2 ----------------
__global__ void prep_e(const float* __restrict__ emb){
  int k = blockIdx.x, c = threadIdx.x;
  float v = emb[k * C_DIM + c];
  uint32_t s0, s1;
  split2(v * ESCALE, s0, s1);
  g_es[(0u * K_CODES + k) * C_DIM + c] = __ushort_as_half((unsigned short)s0);
  g_es[(1u * K_CODES + k) * C_DIM + c] = __ushort_as_half((unsigned short)s1);
  __shared__ float red[C_DIM];
  red[c] = __fmul_rn(v, v);
  __syncthreads();
  for (int s = 128; s > 0; s >>= 1){
    if (c < s) red[c] = __fadd_rn(red[c], red[c + s]);
    __syncthreads();
  }
  if (c == 0) g_e2[k] = red[0];
}

// ---------------- main: m32n64 warp tiles, 16c stages, 2 CTAs/SM ----------------
// smem: A[16 kc][2 s][64 r][16 c] = 64K | B[2 buf][2 s][256 code][16 c] = 32K
//       e2s 4K | z2s 256 | sminv 1K | smini 1K | sidx 256 | red 1K
#define SM_A      0
#define SM_B      65536
#define OFF_E2S   98304
#define OFF_Z2S   102400
#define OFF_SMINV 102656
#define OFF_SMINI 103680
#define OFF_SIDX  104704
#define OFF_RED   104960
#define SM_TOTAL  105984

__global__ __launch_bounds__(256, 2) void vq_main(const float* __restrict__ z,
                                                  const float* __restrict__ emb,
                                                  float* __restrict__ out,
                                                  int out_size){
  extern __shared__ char smem[];
  const uint32_t sb = smem_u32(smem);
  float* e2s   = (float*)(smem + OFF_E2S);
  float* z2s   = (float*)(smem + OFF_Z2S);
  float* sminv = (float*)(smem + OFF_SMINV);
  int*   smini = (int*)(smem + OFF_SMINI);
  int*   sidx  = (int*)(smem + OFF_SIDX);
  float* red   = (float*)(smem + OFF_RED);

  const int t = threadIdx.x, w = t >> 5, l = t & 31;
  const int wm = (w & 1) * 32;        // 2 m-warps x 32 rows
  const int g  = w >> 1;              // 4 n-warp groups
  const int wn = g * 64;              // 64 codes per warp within 256-code tile
  const int n0 = blockIdx.x * ROWS_CTA;
  const int b  = n0 >> 12, hw0 = n0 & 4095;
  const float* zb = z + (size_t)b * (C_DIM * HWSZ) + hw0;

  // ---- B cp.async: one stage = [2 s][256 code][16 c] = 16KB, 32B rows ----
  auto issue = [&](int stage){
    const int nt2 = stage >> 4, kc2 = stage & 15, buf2 = stage & 1;
    #pragma unroll
    for (int i = 0; i < 4; ++i){
      int id = t + i * 256;            // 0..1023 x 16B
      int s = id >> 9, rem = id & 511;
      int code = rem >> 1, j = rem & 1;
      const __half* src = g_es + ((size_t)s * K_CODES + nt2 * 256 + code) * C_DIM + kc2 * 16 + j * 8;
      CPASYNC16(sb + SM_B + buf2 * 16384 + s * 8192 + swz((uint32_t)(code * 32 + j * 16)), src);
    }
    CPCOMMIT();
  };

  issue(0);
  issue(1);

  // ---- phase 1: 4 thr/row split z -> A smem (32B rows); t<64 computes z2 ----
  {
    const int row = t & 63, q = t >> 6;   // q covers dims [q*64, q*64+64)
    #pragma unroll
    for (int cg = 0; cg < 8; ++cg){
      uint32_t p0[4], p1[4];
      #pragma unroll
      for (int j2 = 0; j2 < 4; ++j2){
        int c = q * 64 + cg * 8 + j2 * 2;
        float va = __ldg(zb + (size_t)c * HWSZ + row);
        float vb = __ldg(zb + (size_t)(c + 1) * HWSZ + row);
        uint32_t a0, a1, b0, b1;
        split2(va, a0, a1); split2(vb, b0, b1);
        p0[j2] = a0 | (b0 << 16);
        p1[j2] = a1 | (b1 << 16);
      }
      int kc = 4 * q + (cg >> 1);
      uint32_t ad = swz((uint32_t)(row * 32 + (cg & 1) * 16));
      STS128(sb + SM_A + kc * 4096 + ad,        p0[0], p0[1], p0[2], p0[3]);
      STS128(sb + SM_A + kc * 4096 + 2048 + ad, p1[0], p1[1], p1[2], p1[3]);
    }
  }
  for (int i = t; i < 1024; i += 256) e2s[i] = g_e2[i];
  sminv[t] = 3.4028235e38f; smini[t] = 0;
  if (t < 64){
    float acc2 = 0.f;
    #pragma unroll 8
    for (int c = 0; c < 256; ++c){
      float v = __ldg(zb + (size_t)c * HWSZ + t);
      acc2 = __fadd_rn(acc2, __fmul_rn(v, v));
    }
    z2s[t] = acc2;
  }
  __syncthreads();

  float acc[2][8][4];

  for (int st = 0; st < 64; ++st){
    const int nt = st >> 4, kc = st & 15, buf = st & 1;

    if (st < 63) asm volatile("cp.async.wait_group 1;" ::: "memory");
    else         asm volatile("cp.async.wait_group 0;" ::: "memory");
    __syncthreads();

    if (kc == 0){
      #pragma unroll
      for (int ma = 0; ma < 2; ++ma)
        #pragma unroll
        for (int na = 0; na < 8; ++na)
          #pragma unroll
          for (int q = 0; q < 4; ++q) acc[ma][na][q] = 0.f;
    }

    const uint32_t Ab = sb + SM_A + (uint32_t)kc * 4096;
    const uint32_t Bb = sb + SM_B + (uint32_t)buf * 16384;

    uint32_t af[2][4], bf0[8][2], bf1[8][2];
    // A split-0 fragments
    #pragma unroll
    for (int ma = 0; ma < 2; ++ma){
      uint32_t row = (uint32_t)(wm + ma * 16 + (l & 7) + ((l >> 3) & 1) * 8);
      LDSM_X4(af[ma][0], af[ma][1], af[ma][2], af[ma][3],
              Ab + swz(row * 32 + ((l >> 4) << 4)));
    }
    // B split-0 and split-1 fragments (64 codes)
    #pragma unroll
    for (int p = 0; p < 4; ++p){
      uint32_t nrow = (uint32_t)(wn + p * 16 + ((l >> 4) << 3) + (l & 7));
      uint32_t boff = swz(nrow * 32 + (((l >> 3) & 1) << 4));
      LDSM_X4(bf0[2*p][0], bf0[2*p][1], bf0[2*p+1][0], bf0[2*p+1][1], Bb + boff);
      LDSM_X4(bf1[2*p][0], bf1[2*p][1], bf1[2*p+1][0], bf1[2*p+1][1], Bb + 8192 + boff);
    }
    // pass 1: A0*B0
    #pragma unroll
    for (int ma = 0; ma < 2; ++ma)
      #pragma unroll
      for (int na = 0; na < 8; ++na)
        MMA16816(acc[ma][na][0], acc[ma][na][1], acc[ma][na][2], acc[ma][na][3],
                 af[ma][0], af[ma][1], af[ma][2], af[ma][3], bf0[na][0], bf0[na][1]);
    // pass 2: A0*B1
    #pragma unroll
    for (int ma = 0; ma < 2; ++ma)
      #pragma unroll
      for (int na = 0; na < 8; ++na)
        MMA16816(acc[ma][na][0], acc[ma][na][1], acc[ma][na][2], acc[ma][na][3],
                 af[ma][0], af[ma][1], af[ma][2], af[ma][3], bf1[na][0], bf1[na][1]);
    // A split-1 fragments (reuse af regs)
    #pragma unroll
    for (int ma = 0; ma < 2; ++ma){
      uint32_t row = (uint32_t)(wm + ma * 16 + (l & 7) + ((l >> 3) & 1) * 8);
      LDSM_X4(af[ma][0], af[ma][1], af[ma][2], af[ma][3],
              Ab + 2048 + swz(row * 32 + ((l >> 4) << 4)));
    }
    // pass 3: A1*B0
    #pragma unroll
    for (int ma = 0; ma < 2; ++ma)
      #pragma unroll
      for (int na = 0; na < 8; ++na)
        MMA16816(acc[ma][na][0], acc[ma][na][1], acc[ma][na][2], acc[ma][na][3],
                 af[ma][0], af[ma][1], af[ma][2], af[ma][3], bf0[na][0], bf0[na][1]);

    __syncthreads();
    if (st + 2 < 64) issue(st + 2);

    // ---- per-nt argmin: codes ascending per thread, 4-lane shuffle, smem merge ----
    if (kc == 15){
      #pragma unroll
      for (int ma = 0; ma < 2; ++ma){
        #pragma unroll
        for (int h = 0; h < 2; ++h){
          int row = wm + ma * 16 + (l >> 2) + h * 8;
          float z2v = z2s[row];
          float bv = 3.4028235e38f; int bi = 0;
          #pragma unroll
          for (int na = 0; na < 8; ++na){
            #pragma unroll
            for (int c2 = 0; c2 < 2; ++c2){
              int code = nt * 256 + wn + na * 8 + (l & 3) * 2 + c2;
              float dot = acc[ma][na][h * 2 + c2] * EINVSCALE;
              float sd = __fadd_rn(z2v, e2s[code]);
              float dist = __fsub_rn(sd, __fmul_rn(2.0f, dot));
              if (dist < bv){ bv = dist; bi = code; }
            }
          }
          #pragma unroll
          for (int m = 1; m <= 2; m <<= 1){
            float ov = __shfl_xor_sync(0xffffffffu, bv, m);
            int   oi = __shfl_xor_sync(0xffffffffu, bi, m);
            if (ov < bv || (ov == bv && oi < bi)){ bv = ov; bi = oi; }
          }
          if ((l & 3) == 0){
            int idx = g * 64 + row;
            if (bv < sminv[idx] || (bv == sminv[idx] && bi < smini[idx])){
              sminv[idx] = bv; smini[idx] = bi;
            }
          }
        }
      }
    }
  }
  __syncthreads();

  // ---- cross-group combine, idx output ----
  if (t < 64){
    float bv = sminv[t]; int bi = smini[t];
    #pragma unroll
    for (int gg = 1; gg < 4; ++gg){
      float ov = sminv[gg * 64 + t]; int oi = smini[gg * 64 + t];
      if (ov < bv || (ov == bv && oi < bi)){ bv = ov; bi = oi; }
    }
    sidx[t] = bi;
    if (out_size >= NZQ + N_ROWS) out[NZQ + n0 + t] = (float)bi;
  }
  __syncthreads();

  // ---- fused epilogue: gather zq, straight-through output, loss partial ----
  {
    const int i = t & 63, q = t >> 6;
    const int code = sidx[i];
    const float* erow = emb + (size_t)code * C_DIM;
    float lacc = 0.f;
    const bool wr = (out_size >= NZQ);
    #pragma unroll 4
    for (int c = q; c < 256; c += 4){
      float e  = __ldg(&erow[c]);
      size_t a = (size_t)b * (C_DIM * HWSZ) + hw0 + (size_t)c * HWSZ + i;
      float zp = z[a];
      float d  = __fsub_rn(e, zp);
      if (wr) out[a] = __fadd_rn(zp, d);
      lacc = __fadd_rn(lacc, __fmul_rn(d, d));
    }
    red[t] = lacc;
    __syncthreads();
    for (int s = 128; s > 0; s >>= 1){
      if (t < s) red[t] = __fadd_rn(red[t], red[t + s]);
      __syncthreads();
    }
    if (t == 0) g_partial[blockIdx.x] = red[0];
  }
}

// ---------------- final loss ----------------
__global__ void vq_fin(float* __restrict__ out, int out_size){
  __shared__ double dred[256];
  const int t = threadIdx.x;
  double s = 0.0;
  for (int ii = t; ii < GRID; ii += 256) s += (double)g_partial[ii];
  dred[t] = s;
  __syncthreads();
  for (int k = 128; k > 0; k >>= 1){
    if (t < k) dred[t] += dred[t + k];
    __syncthreads();
  }
  if (t == 0 && out_size >= NZQ + N_ROWS + 1){
    float m1 = (float)(dred[0] / 33554432.0);
    float loss = __fsub_rn(m1, __fmul_rn(0.25f, m1));
    out[NZQ + N_ROWS] = loss;
  }
}

extern "C" void kernel_launch(void* const* d_in, const int* in_sizes, int n_in,
                              void* d_out, int out_size){
  const float* z   = (const float*)d_in[0];
  const float* emb = (const float*)d_in[1];
  float* out = (float*)d_out;
  (void)in_sizes; (void)n_in;

  cudaFuncSetAttribute(vq_main, cudaFuncAttributeMaxDynamicSharedMemorySize, SM_TOTAL);

  prep_e<<<K_CODES, C_DIM>>>(emb);
  vq_main<<<GRID, 256, SM_TOTAL>>>(z, emb, out, out_size);
  vq_fin<<<1, 256>>>(out, out_size);
}

// round 10
// speedup vs baseline: 1.0195x; 1.0195x over previous
#include <cuda_runtime.h>
#include <cuda_fp16.h>
#include <cstdint>

#define N_ROWS  131072
#define C_DIM   256
#define K_CODES 1024
#define NZQ     33554432
#define HWSZ    4096
#define ROWS_CTA 64
#define GRID    (N_ROWS / ROWS_CTA)

#define ESCALE    4096.0f          // 2^12: lift emb splits out of fp16 subnormal range
#define EINVSCALE 0.000244140625f  // 2^-12 (exact)

__device__ __half g_es[2u * K_CODES * C_DIM];   // emb fp16 2-splits of (e * 2^12)
__device__ float  g_e2[K_CODES];
__device__ float  g_partial[GRID];

__device__ __forceinline__ uint32_t smem_u32(const void* p){
  uint32_t a;
  asm("{ .reg .u64 t; cvta.to.shared.u64 t, %1; cvt.u32.u64 %0, t; }" : "=r"(a) : "l"(p));
  return a;
}
__device__ __forceinline__ uint32_t swz(uint32_t off){ return off ^ ((off >> 3) & 0x70); }

__device__ __forceinline__ void split2(float v, uint32_t &s0, uint32_t &s1){
  __half h0 = __float2half_rn(v);
  float r  = __fsub_rn(v, __half2float(h0));
  __half h1 = __float2half_rn(r);
  s0 = (uint32_t)__half_as_ushort(h0);
  s1 = (uint32_t)__half_as_ushort(h1);
}

#define CPASYNC16(dst, src) \
  asm volatile("cp.async.cg.shared.global [%0], [%1], 16;" :: "r"(dst), "l"(src))
#define CPCOMMIT() asm volatile("cp.async.commit_group;")

#define LDSM_X4(r0,r1,r2,r3,addr) \
  asm volatile("ldmatrix.sync.aligned.m8n8.x4.shared.b16 {%0,%1,%2,%3}, [%4];" \
    : "=r"(r0), "=r"(r1), "=r"(r2), "=r"(r3) : "r"(addr))

#define MMA16816(c0,c1,c2,c3,a0,a1,a2,a3,b0,b1) \
  asm volatile("mma.sync.aligned.m16n8k16.row.col.f32.f16.f16.f32 " \
    "{%0,%1,%2,%3}, {%4,%5,%6,%7}, {%8,%9}, {%0,%1,%2,%3};" \
    : "+f"(c0), "+f"(c1), "+f"(c2), "+f"(c3) \
    : "r"(a0), "r"(a1), "r"(a2), "r"(a3), "r"(b0), "r"(b1))

#define STS128(addr, a0, a1, a2, a3) \
  asm volatile("st.shared.v4.b32 [%0], {%1,%2,%3,%4};" :: "r"(addr), "r"(a0), "r"(a1), "r"(a2), "r"(a3) : "memory")

// ---------------- prep: emb fp16 splits (scaled) + ||e||^2 ----------------
__global__ void prep_e(const float* __restrict__ emb){
  int k = blockIdx.x, c = threadIdx.x;
  float v = emb[k * C_DIM + c];
  uint32_t s0, s1;
  split2(v * ESCALE, s0, s1);
  g_es[(0u * K_CODES + k) * C_DIM + c] = __ushort_as_half((unsigned short)s0);
  g_es[(1u * K_CODES + k) * C_DIM + c] = __ushort_as_half((unsigned short)s1);
  __shared__ float red[C_DIM];
  red[c] = __fmul_rn(v, v);
  __syncthreads();
  for (int s = 128; s > 0; s >>= 1){
    if (c < s) red[c] = __fadd_rn(red[c], red[c + s]);
    __syncthreads();
  }
  if (c == 0) g_e2[k] = red[0];
}

// no-op: aligns vq_main at launch index 3 so ncu captures it
__global__ void dummy_k(){}

// ---------------- main: m32n64 warp tiles, 16c stages, 2 CTAs/SM, reg-staged frags ----------------
// smem: A[16 kc][2 s][64 r][16 c] = 64K | B[2 buf][2 s][256 code][16 c] = 32K
//       e2s 4K | z2s 256 | sminv 1K | smini 1K | sidx 256 | red 1K
#define SM_A      0
#define SM_B      65536
#define OFF_E2S   98304
#define OFF_Z2S   102400
#define OFF_SMINV 102656
#define OFF_SMINI 103680
#define OFF_SIDX  104704
#define OFF_RED   104960
#define SM_TOTAL  105984

__global__ __launch_bounds__(256, 2) void vq_main(const float* __restrict__ z,
                                                  const float* __restrict__ emb,
                                                  float* __restrict__ out,
                                                  int out_size){
  extern __shared__ char smem[];
  const uint32_t sb = smem_u32(smem);
  float* e2s   = (float*)(smem + OFF_E2S);
  float* z2s   = (float*)(smem + OFF_Z2S);
  float* sminv = (float*)(smem + OFF_SMINV);
  int*   smini = (int*)(smem + OFF_SMINI);
  int*   sidx  = (int*)(smem + OFF_SIDX);
  float* red   = (float*)(smem + OFF_RED);

  const int t = threadIdx.x, w = t >> 5, l = t & 31;
  const int wm = (w & 1) * 32;        // 2 m-warps x 32 rows
  const int g  = w >> 1;              // 4 n-warp groups
  const int wn = g * 64;              // 64 codes per warp within 256-code tile
  const int n0 = blockIdx.x * ROWS_CTA;
  const int b  = n0 >> 12, hw0 = n0 & 4095;
  const float* zb = z + (size_t)b * (C_DIM * HWSZ) + hw0;

  // ---- B cp.async: one stage = [2 s][256 code][16 c] = 16KB, 32B rows ----
  auto issue = [&](int stage){
    const int nt2 = stage >> 4, kc2 = stage & 15, buf2 = stage & 1;
    #pragma unroll
    for (int i = 0; i < 4; ++i){
      int id = t + i * 256;            // 0..1023 x 16B
      int s = id >> 9, rem = id & 511;
      int code = rem >> 1, j = rem & 1;
      const __half* src = g_es + ((size_t)s * K_CODES + nt2 * 256 + code) * C_DIM + kc2 * 16 + j * 8;
      CPASYNC16(sb + SM_B + buf2 * 16384 + s * 8192 + swz((uint32_t)(code * 32 + j * 16)), src);
    }
    CPCOMMIT();
  };

  issue(0);
  issue(1);

  // ---- phase 1: 4 thr/row split z -> A smem (32B rows); t<64 computes z2 ----
  {
    const int row = t & 63, q = t >> 6;   // q covers dims [q*64, q*64+64)
    #pragma unroll
    for (int cg = 0; cg < 8; ++cg){
      uint32_t p0[4], p1[4];
      #pragma unroll
      for (int j2 = 0; j2 < 4; ++j2){
        int c = q * 64 + cg * 8 + j2 * 2;
        float va = __ldg(zb + (size_t)c * HWSZ + row);
        float vb = __ldg(zb + (size_t)(c + 1) * HWSZ + row);
        uint32_t a0, a1, b0, b1;
        split2(va, a0, a1); split2(vb, b0, b1);
        p0[j2] = a0 | (b0 << 16);
        p1[j2] = a1 | (b1 << 16);
      }
      int kc = 4 * q + (cg >> 1);
      uint32_t ad = swz((uint32_t)(row * 32 + (cg & 1) * 16));
      STS128(sb + SM_A + kc * 4096 + ad,        p0[0], p0[1], p0[2], p0[3]);
      STS128(sb + SM_A + kc * 4096 + 2048 + ad, p1[0], p1[1], p1[2], p1[3]);
    }
  }
  for (int i = t; i < 1024; i += 256) e2s[i] = g_e2[i];
  sminv[t] = 3.4028235e38f; smini[t] = 0;
  if (t < 64){
    float acc2 = 0.f;
    #pragma unroll 8
    for (int c = 0; c < 256; ++c){
      float v = __ldg(zb + (size_t)c * HWSZ + t);
      acc2 = __fadd_rn(acc2, __fmul_rn(v, v));
    }
    z2s[t] = acc2;
  }
  __syncthreads();

  float acc[2][8][4];

  // fragment address bases (loop-invariant)
  const uint32_t arow0 = (uint32_t)(wm + (l & 7) + ((l >> 3) & 1) * 8);
  const uint32_t aoff0 = swz(arow0 * 32 + ((l >> 4) << 4));
  const uint32_t aoff1 = swz((arow0 + 16) * 32 + ((l >> 4) << 4));
  uint32_t boffs[4];
  #pragma unroll
  for (int p = 0; p < 4; ++p){
    uint32_t nrow = (uint32_t)(wn + p * 16 + ((l >> 4) << 3) + (l & 7));
    boffs[p] = swz(nrow * 32 + (((l >> 3) & 1) << 4));
  }

  for (int st = 0; st < 64; ++st){
    const int nt = st >> 4, kc = st & 15, buf = st & 1;

    if (st < 63) asm volatile("cp.async.wait_group 1;" ::: "memory");
    else         asm volatile("cp.async.wait_group 0;" ::: "memory");
    __syncthreads();

    if (kc == 0){
      #pragma unroll
      for (int ma = 0; ma < 2; ++ma)
        #pragma unroll
        for (int na = 0; na < 8; ++na)
          #pragma unroll
          for (int q = 0; q < 4; ++q) acc[ma][na][q] = 0.f;
    }

    const uint32_t Ab = sb + SM_A + (uint32_t)kc * 4096;
    const uint32_t Bb = sb + SM_B + (uint32_t)buf * 16384;

    // --- reg-staged fragment schedule: peak live = acc64 + af0 8 + af1 8 + bf 16 ---
    uint32_t af0[2][4], af1[2][4], bf[8][2];

    // A split-0
    LDSM_X4(af0[0][0], af0[0][1], af0[0][2], af0[0][3], Ab + aoff0);
    LDSM_X4(af0[1][0], af0[1][1], af0[1][2], af0[1][3], Ab + aoff1);
    // B split-0
    #pragma unroll
    for (int p = 0; p < 4; ++p)
      LDSM_X4(bf[2*p][0], bf[2*p][1], bf[2*p+1][0], bf[2*p+1][1], Bb + boffs[p]);

    // pass 1: A0*B0
    #pragma unroll
    for (int ma = 0; ma < 2; ++ma)
      #pragma unroll
      for (int na = 0; na < 8; ++na)
        MMA16816(acc[ma][na][0], acc[ma][na][1], acc[ma][na][2], acc[ma][na][3],
                 af0[ma][0], af0[ma][1], af0[ma][2], af0[ma][3], bf[na][0], bf[na][1]);

    // A split-1
    LDSM_X4(af1[0][0], af1[0][1], af1[0][2], af1[0][3], Ab + 2048 + aoff0);
    LDSM_X4(af1[1][0], af1[1][1], af1[1][2], af1[1][3], Ab + 2048 + aoff1);

    // pass 2: A1*B0 (B0 dead after)
    #pragma unroll
    for (int ma = 0; ma < 2; ++ma)
      #pragma unroll
      for (int na = 0; na < 8; ++na)
        MMA16816(acc[ma][na][0], acc[ma][na][1], acc[ma][na][2], acc[ma][na][3],
                 af1[ma][0], af1[ma][1], af1[ma][2], af1[ma][3], bf[na][0], bf[na][1]);

    // B split-1 (reuse bf regs)
    #pragma unroll
    for (int p = 0; p < 4; ++p)
      LDSM_X4(bf[2*p][0], bf[2*p][1], bf[2*p+1][0], bf[2*p+1][1], Bb + 8192 + boffs[p]);

    // pass 3: A0*B1
    #pragma unroll
    for (int ma = 0; ma < 2; ++ma)
      #pragma unroll
      for (int na = 0; na < 8; ++na)
        MMA16816(acc[ma][na][0], acc[ma][na][1], acc[ma][na][2], acc[ma][na][3],
                 af0[ma][0], af0[ma][1], af0[ma][2], af0[ma][3], bf[na][0], bf[na][1]);

    __syncthreads();
    if (st + 2 < 64) issue(st + 2);

    // ---- per-nt argmin: codes ascending per thread, 4-lane shuffle, smem merge ----
    if (kc == 15){
      #pragma unroll
      for (int ma = 0; ma < 2; ++ma){
        #pragma unroll
        for (int h = 0; h < 2; ++h){
          int row = wm + ma * 16 + (l >> 2) + h * 8;
          float z2v = z2s[row];
          float bv = 3.4028235e38f; int bi = 0;
          #pragma unroll
          for (int na = 0; na < 8; ++na){
            #pragma unroll
            for (int c2 = 0; c2 < 2; ++c2){
              int code = nt * 256 + wn + na * 8 + (l & 3) * 2 + c2;
              float dot = acc[ma][na][h * 2 + c2] * EINVSCALE;
              float sd = __fadd_rn(z2v, e2s[code]);
              float dist = __fsub_rn(sd, __fmul_rn(2.0f, dot));
              if (dist < bv){ bv = dist; bi = code; }
            }
          }
          #pragma unroll
          for (int m = 1; m <= 2; m <<= 1){
            float ov = __shfl_xor_sync(0xffffffffu, bv, m);
            int   oi = __shfl_xor_sync(0xffffffffu, bi, m);
            if (ov < bv || (ov == bv && oi < bi)){ bv = ov; bi = oi; }
          }
          if ((l & 3) == 0){
            int idx = g * 64 + row;
            if (bv < sminv[idx] || (bv == sminv[idx] && bi < smini[idx])){
              sminv[idx] = bv; smini[idx] = bi;
            }
          }
        }
      }
    }
  }
  __syncthreads();

  // ---- cross-group combine, idx output ----
  if (t < 64){
    float bv = sminv[t]; int bi = smini[t];
    #pragma unroll
    for (int gg = 1; gg < 4; ++gg){
      float ov = sminv[gg * 64 + t]; int oi = smini[gg * 64 + t];
      if (ov < bv || (ov == bv && oi < bi)){ bv = ov; bi = oi; }
    }
    sidx[t] = bi;
    if (out_size >= NZQ + N_ROWS) out[NZQ + n0 + t] = (float)bi;
  }
  __syncthreads();

  // ---- fused epilogue: gather zq, straight-through output, loss partial ----
  {
    const int i = t & 63, q = t >> 6;
    const int code = sidx[i];
    const float* erow = emb + (size_t)code * C_DIM;
    float lacc = 0.f;
    const bool wr = (out_size >= NZQ);
    #pragma unroll 4
    for (int c = q; c < 256; c += 4){
      float e  = __ldg(&erow[c]);
      size_t a = (size_t)b * (C_DIM * HWSZ) + hw0 + (size_t)c * HWSZ + i;
      float zp = z[a];
      float d  = __fsub_rn(e, zp);
      if (wr) out[a] = __fadd_rn(zp, d);
      lacc = __fadd_rn(lacc, __fmul_rn(d, d));
    }
    red[t] = lacc;
    __syncthreads();
    for (int s = 128; s > 0; s >>= 1){
      if (t < s) red[t] = __fadd_rn(red[t], red[t + s]);
      __syncthreads();
    }
    if (t == 0) g_partial[blockIdx.x] = red[0];
  }
}

// ---------------- final loss ----------------
__global__ void vq_fin(float* __restrict__ out, int out_size){
  __shared__ double dred[256];
  const int t = threadIdx.x;
  double s = 0.0;
  for (int ii = t; ii < GRID; ii += 256) s += (double)g_partial[ii];
  dred[t] = s;
  __syncthreads();
  for (int k = 128; k > 0; k >>= 1){
    if (t < k) dred[t] += dred[t + k];
    __syncthreads();
  }
  if (t == 0 && out_size >= NZQ + N_ROWS + 1){
    float m1 = (float)(dred[0] / 33554432.0);
    float loss = __fsub_rn(m1, __fmul_rn(0.25f, m1));
    out[NZQ + N_ROWS] = loss;
  }
}

extern "C" void kernel_launch(void* const* d_in, const int* in_sizes, int n_in,
                              void* d_out, int out_size){
  const float* z   = (const float*)d_in[0];
  const float* emb = (const float*)d_in[1];
  float* out = (float*)d_out;
  (void)in_sizes; (void)n_in;

  cudaFuncSetAttribute(vq_main, cudaFuncAttributeMaxDynamicSharedMemorySize, SM_TOTAL);

  prep_e<<<K_CODES, C_DIM>>>(emb);      // launch 0
  dummy_k<<<1, 32>>>();                 // launch 1
  dummy_k<<<1, 32>>>();                 // launch 2
  vq_main<<<GRID, 256, SM_TOTAL>>>(z, emb, out, out_size);  // launch 3 (ncu target)
  dummy_k<<<1, 32>>>();                 // launch 4
  vq_fin<<<1, 256>>>(out, out_size);    // launch 5
}